// round 5
// baseline (speedup 1.0000x reference)
#include <cuda_runtime.h>

#define Nn 50000
#define Ee 800000
#define Dd 96

// ---------------------------------------------------------------------------
// Scratch (__device__ globals — no allocation allowed).
// float4-typed so all 16B vector accesses are guaranteed aligned.
// ---------------------------------------------------------------------------
__device__ float4 g_agg4[Nn * Dd / 4];   // aggregated neighbor features
__device__ float4 g_h4[Nn * Dd / 4];     // hidden layer output
__device__ int    g_deg[Nn];             // per-dst degree
__device__ int    g_off[Nn];             // exclusive CSR offsets
__device__ int    g_pos[Nn];             // fill cursors
__device__ int    g_srcs[Ee];            // CSR column indices (src node ids)

// ---------------------------------------------------------------------------
// CSR build step 1: zero counters
// ---------------------------------------------------------------------------
__global__ void k_zero_counts() {
    int i = blockIdx.x * blockDim.x + threadIdx.x;
    if (i < Nn) { g_deg[i] = 0; g_pos[i] = 0; }
}

// CSR build step 2: histogram of dst  (edge_index is int32: [2, E] row-major)
__global__ void __launch_bounds__(256)
k_hist(const int* __restrict__ ei) {
    int e = blockIdx.x * blockDim.x + threadIdx.x;
    if (e >= Ee) return;
    int d = ei[Ee + e];
    if ((unsigned)d < (unsigned)Nn) atomicAdd(&g_deg[d], 1);
}

// CSR build step 3: exclusive prefix sum over g_deg (single block)
__global__ void k_scan() {
    __shared__ int sm[1024];
    __shared__ int carry;
    if (threadIdx.x == 0) carry = 0;
    __syncthreads();
    for (int base = 0; base < Nn; base += 1024) {
        int i = base + (int)threadIdx.x;
        int v = (i < Nn) ? g_deg[i] : 0;
        sm[threadIdx.x] = v;
        __syncthreads();
        for (int off = 1; off < 1024; off <<= 1) {
            int t = (threadIdx.x >= off) ? sm[threadIdx.x - off] : 0;
            __syncthreads();
            sm[threadIdx.x] += t;
            __syncthreads();
        }
        if (i < Nn) g_off[i] = carry + sm[threadIdx.x] - v;  // exclusive
        __syncthreads();
        if (threadIdx.x == 1023) carry += sm[1023];
        __syncthreads();
    }
}

// CSR build step 4: fill column indices
__global__ void __launch_bounds__(256)
k_fill(const int* __restrict__ ei) {
    int e = blockIdx.x * blockDim.x + threadIdx.x;
    if (e >= Ee) return;
    int s = ei[e];
    int d = ei[Ee + e];
    if ((unsigned)s >= (unsigned)Nn || (unsigned)d >= (unsigned)Nn) return;
    int slot = g_off[d] + atomicAdd(&g_pos[d], 1);
    g_srcs[slot] = s;
}

// ---------------------------------------------------------------------------
// Atomic-free segment sum: one warp per dst node.
// Lane c accumulates columns c, c+32, c+64. Source rows are 384B contiguous
// and the whole feature matrix fits in L2.
// ---------------------------------------------------------------------------
__global__ void __launch_bounds__(256)
k_gather(const float* __restrict__ xin, int use_h) {
    int warp = (blockIdx.x * blockDim.x + threadIdx.x) >> 5;
    if (warp >= Nn) return;
    int lane = threadIdx.x & 31;
    const float* feat = use_h ? (const float*)g_h4 : xin;
    int j   = g_off[warp];
    int end = j + g_deg[warp];
    float a0 = 0.f, a1 = 0.f, a2 = 0.f;
    // unroll by 2 for memory-level parallelism
    for (; j + 1 < end; j += 2) {
        int s0 = g_srcs[j], s1 = g_srcs[j + 1];
        const float* r0 = feat + s0 * Dd;
        const float* r1 = feat + s1 * Dd;
        float v00 = r0[lane], v01 = r0[lane + 32], v02 = r0[lane + 64];
        float v10 = r1[lane], v11 = r1[lane + 32], v12 = r1[lane + 64];
        a0 += v00 + v10; a1 += v01 + v11; a2 += v02 + v12;
    }
    if (j < end) {
        const float* r0 = feat + g_srcs[j] * Dd;
        a0 += r0[lane]; a1 += r0[lane + 32]; a2 += r0[lane + 64];
    }
    float* o = (float*)g_agg4 + warp * Dd;
    o[lane] = a0; o[lane + 32] = a1; o[lane + 64] = a2;
}

// ---------------------------------------------------------------------------
// Fused dual matvec: out[r] = relu?( agg[r] @ W_rel + bias + X[r] @ W_root )
// Static smem only (48KB): W 96x96 (36KB) + A tile 32x96 (12KB).
// Block: 192 threads = (24 float4-col groups) x (8 row groups);
// each thread computes 4 rows x 4 cols. Two passes share smem buffers.
// ---------------------------------------------------------------------------
#define TILE_ROWS 32

__global__ void __launch_bounds__(192)
k_gemm_dual(const float* __restrict__ xin,
            const float* __restrict__ Wrel,
            const float* __restrict__ bias,
            const float* __restrict__ Wroot,
            float* out_param,
            int use_h_in, int use_h_out, int do_relu) {
    __shared__ float shW[96 * 96];
    __shared__ float shA[TILE_ROWS * 96];

    const float* X = use_h_in ? (const float*)g_h4 : xin;
    float*       O = use_h_out ? (float*)g_h4 : out_param;

    const int tx = threadIdx.x;      // 0..23
    const int ty = threadIdx.y;      // 0..7
    const int tid = ty * 24 + tx;    // 0..191
    const int row0 = blockIdx.x * TILE_ROWS;

    float4 acc[4];
#pragma unroll
    for (int i = 0; i < 4; i++) acc[i] = make_float4(0.f, 0.f, 0.f, 0.f);

    for (int pass = 0; pass < 2; pass++) {
        const float* W = pass ? Wroot : Wrel;
        const float* A = pass ? X : (const float*)g_agg4;
        __syncthreads();
#pragma unroll
        for (int i = 0; i < 12; i++)
            reinterpret_cast<float4*>(shW)[tid + 192 * i] =
                reinterpret_cast<const float4*>(W)[tid + 192 * i];
#pragma unroll
        for (int i = 0; i < 4; i++) {
            int idx = tid + 192 * i;
            int r = idx / 24;
            int kc = idx - r * 24;
            int gr = row0 + r;
            float4 v = make_float4(0.f, 0.f, 0.f, 0.f);
            if (gr < Nn) v = reinterpret_cast<const float4*>(A + gr * Dd)[kc];
            reinterpret_cast<float4*>(shA + r * Dd)[kc] = v;
        }
        __syncthreads();

#pragma unroll 4
        for (int k = 0; k < Dd; k++) {
            float4 w = reinterpret_cast<float4*>(shW + k * Dd)[tx];
#pragma unroll
            for (int i = 0; i < 4; i++) {
                float a = shA[(ty * 4 + i) * Dd + k];
                acc[i].x = fmaf(a, w.x, acc[i].x);
                acc[i].y = fmaf(a, w.y, acc[i].y);
                acc[i].z = fmaf(a, w.z, acc[i].z);
                acc[i].w = fmaf(a, w.w, acc[i].w);
            }
        }
    }

    float4 bv = reinterpret_cast<const float4*>(bias)[tx];
#pragma unroll
    for (int i = 0; i < 4; i++) {
        int gr = row0 + ty * 4 + i;
        if (gr < Nn) {
            float4 o;
            o.x = acc[i].x + bv.x;
            o.y = acc[i].y + bv.y;
            o.z = acc[i].z + bv.z;
            o.w = acc[i].w + bv.w;
            if (do_relu) {
                o.x = fmaxf(o.x, 0.f);
                o.y = fmaxf(o.y, 0.f);
                o.z = fmaxf(o.z, 0.f);
                o.w = fmaxf(o.w, 0.f);
            }
            reinterpret_cast<float4*>(O + gr * Dd)[tx] = o;
        }
    }
}

// ---------------------------------------------------------------------------
extern "C" void kernel_launch(void* const* d_in, const int* in_sizes, int n_in,
                              void* d_out, int out_size) {
    const float* x    = (const float*)d_in[0];
    const int*   ei   = (const int*)d_in[1];   // int32! (JAX x64 disabled)
    const float* W1r  = (const float*)d_in[2];
    const float* b1   = (const float*)d_in[3];
    const float* W1o  = (const float*)d_in[4];
    const float* W2r  = (const float*)d_in[5];
    const float* b2   = (const float*)d_in[6];
    const float* W2o  = (const float*)d_in[7];
    float*       out  = (float*)d_out;

    const int node_blocks = (Nn + 255) / 256;
    const int edge_blocks = (Ee + 255) / 256;
    const int gather_blocks = (Nn * 32 + 255) / 256;
    const int gemm_blocks = (Nn + TILE_ROWS - 1) / TILE_ROWS;

    // ---- CSR build (once; shared by both layers) ----
    k_zero_counts<<<node_blocks, 256>>>();
    k_hist<<<edge_blocks, 256>>>(ei);
    k_scan<<<1, 1024>>>();
    k_fill<<<edge_blocks, 256>>>(ei);

    // ---- Layer 1: h = relu(agg(x) @ W1r + b1 + x @ W1o) ----
    k_gather<<<gather_blocks, 256>>>(x, /*use_h=*/0);
    k_gemm_dual<<<gemm_blocks, dim3(24, 8)>>>(
        x, W1r, b1, W1o, out, /*use_h_in=*/0, /*use_h_out=*/1, /*do_relu=*/1);

    // ---- Layer 2: out = agg(h) @ W2r + b2 + h @ W2o ----
    k_gather<<<gather_blocks, 256>>>(x, /*use_h=*/1);
    k_gemm_dual<<<gemm_blocks, dim3(24, 8)>>>(
        x, W2r, b2, W2o, out, /*use_h_in=*/1, /*use_h_out=*/0, /*do_relu=*/0);
}